// round 13
// baseline (speedup 1.0000x reference)
#include <cuda_runtime.h>
#include <cstdint>
#include <math.h>

#define NPTS   131072
#define DIM    768
#define KPT    17
#define MPROTO 10
#define KM     170      // KPT*MPROTO
#define KMP    176      // padded columns for GEMM tiling (16*11)

// ---------------- scratch (__device__ globals; no allocation allowed) --------
__device__ float g_phat[KMP * DIM];     // normalized prototypes, padded rows zero
__device__ float g_rnorm[NPTS];         // 1/max(||feats_n||,1e-12)
__device__ float g_outcls[NPTS * KPT];  // max over m of |sim|
__device__ float g_confeff[NPTS];
__device__ float g_E[NPTS * MPROTO];    // exp(|sim[n, gt_n, m]| / eps)
__device__ float g_cs[3][KM];           // column sums per sinkhorn iter
__device__ float g_c[3][KM];            // column scales per sinkhorn iter
__device__ int   g_B[KPT];              // member counts
__device__ float g_nn[KM];              // n[k,m] counts (sum of conf_eff)
__device__ float g_fbuf[KM * DIM];      // f accumulator
__device__ int   g_sel[NPTS];           // assigned (k*10+m) or -1

struct GKeys { unsigned int a[KPT]; unsigned int b[KPT]; };

// ---------------- threefry2x32 (JAX-compatible, 20 rounds) -------------------
__host__ __device__ inline void threefry2x32(unsigned int k0, unsigned int k1,
                                             unsigned int x0, unsigned int x1,
                                             unsigned int* o0, unsigned int* o1) {
    unsigned int ks[3];
    ks[0] = k0; ks[1] = k1; ks[2] = k0 ^ k1 ^ 0x1BD11BDAu;
    x0 += ks[0]; x1 += ks[1];
    const unsigned int rotA[4] = {13u, 15u, 26u, 6u};
    const unsigned int rotB[4] = {17u, 29u, 16u, 24u};
#pragma unroll
    for (int i = 0; i < 5; i++) {
#pragma unroll
        for (int j = 0; j < 4; j++) {
            unsigned int r = (i & 1) ? rotB[j] : rotA[j];
            x0 += x1;
            x1 = (x1 << r) | (x1 >> (32u - r));
            x1 ^= x0;
        }
        x0 += ks[(i + 1) % 3];
        x1 += ks[(i + 2) % 3] + (unsigned int)(i + 1);
    }
    *o0 = x0; *o1 = x1;
}

// JAX partitionable random_bits: 64-bit counter (hi=0, lo=idx), bits = y0 ^ y1.
// uniform: mantissa-fill -> [0,1), *(1-tiny)+tiny, max(tiny). gumbel = -log(-log(u)).
__device__ __forceinline__ float gumbel_val(unsigned int ka, unsigned int kb,
                                            unsigned int idx) {
    unsigned int y0, y1;
    threefry2x32(ka, kb, 0u, idx, &y0, &y1);
    unsigned int bits = y0 ^ y1;
    float u = __uint_as_float((bits >> 9) | 0x3F800000u) - 1.0f;
    const float tiny = 1.17549435e-38f;
    u = fmaxf(u + tiny, tiny);
    return -logf(-logf(u));
}

// ---------------- block reduction --------------------------------------------
__device__ __forceinline__ float blockReduceSum(float v) {
    __shared__ float sh[33];
    __syncthreads();
    int lane = threadIdx.x & 31, w = threadIdx.x >> 5;
#pragma unroll
    for (int o = 16; o; o >>= 1) v += __shfl_xor_sync(0xffffffffu, v, o);
    if (lane == 0) sh[w] = v;
    __syncthreads();
    int nw = (blockDim.x + 31) >> 5;
    v = (threadIdx.x < nw) ? sh[threadIdx.x] : 0.f;
    if (w == 0) {
#pragma unroll
        for (int o = 16; o; o >>= 1) v += __shfl_xor_sync(0xffffffffu, v, o);
        if (lane == 0) sh[32] = v;
    }
    __syncthreads();
    return sh[32];
}

// ---------------- kernels ----------------------------------------------------
__global__ void k_zero() {
    int i = blockIdx.x * blockDim.x + threadIdx.x;   // 130560 threads
    if (i < KM * DIM) g_fbuf[i] = 0.f;
    if (i < KM) { g_nn[i] = 0.f; g_cs[0][i] = 0.f; g_cs[1][i] = 0.f; g_cs[2][i] = 0.f; }
    if (i < KPT) g_B[i] = 0;
    if (i < (KMP - KM) * DIM) g_phat[KM * DIM + i] = 0.f;   // zero GEMM pad rows
}

__global__ void k_protonorm(const float* __restrict__ protos) {
    int r = blockIdx.x;                 // 0..169
    const float* p = protos + r * DIM;
    float s = 0.f;
    for (int i = threadIdx.x; i < DIM; i += blockDim.x) { float v = p[i]; s += v * v; }
    s = blockReduceSum(s);
    float sc = 1.0f / fmaxf(sqrtf(s), 1e-12f);
    for (int i = threadIdx.x; i < DIM; i += blockDim.x) g_phat[r * DIM + i] = p[i] * sc;
}

__global__ void k_featnorm(const float* __restrict__ feats) {
    int warp = (blockIdx.x * blockDim.x + threadIdx.x) >> 5;
    int lane = threadIdx.x & 31;
    if (warp >= NPTS) return;
    const float4* f = (const float4*)(feats + (size_t)warp * DIM);
    float s = 0.f;
#pragma unroll
    for (int i = 0; i < 6; i++) {
        float4 v = f[lane + i * 32];
        s += v.x * v.x + v.y * v.y + v.z * v.z + v.w * v.w;
    }
#pragma unroll
    for (int o = 16; o; o >>= 1) s += __shfl_xor_sync(0xffffffffu, s, o);
    if (lane == 0) g_rnorm[warp] = 1.0f / fmaxf(sqrtf(s), 1e-12f);
}

// C[N,170] = |(feats . phat^T) * rnorm|, written straight into d_out region 1.
#define TR 64
#define KC 32
__global__ __launch_bounds__(256) void k_gemm(const float* __restrict__ feats,
                                              float* __restrict__ out) {
    __shared__ float As[TR][KC + 4];       // stride 36 floats (144B, 16B-aligned rows)
    __shared__ float Bs[KC][KMP + 1];      // stride 177 -> conflict-free transpose fill
    int tx = threadIdx.x & 15;
    int ty = threadIdx.x >> 4;
    int row0 = blockIdx.x * TR;

    float acc[4][11];
#pragma unroll
    for (int r = 0; r < 4; r++)
#pragma unroll
        for (int j = 0; j < 11; j++) acc[r][j] = 0.f;

    for (int k0 = 0; k0 < DIM; k0 += KC) {
        int t = threadIdx.x;
#pragma unroll
        for (int it = 0; it < 2; it++) {
            int id = t + it * 256;          // 0..511
            int r = id >> 3;
            int q = id & 7;
            float4 v = *(const float4*)(feats + (size_t)(row0 + r) * DIM + k0 + q * 4);
            *(float4*)&As[r][q * 4] = v;
        }
        for (int id = t; id < KMP * 8; id += 256) {
            int km = id >> 3;
            int q = id & 7;
            float4 v = *(const float4*)(g_phat + km * DIM + k0 + q * 4);
            Bs[q * 4 + 0][km] = v.x; Bs[q * 4 + 1][km] = v.y;
            Bs[q * 4 + 2][km] = v.z; Bs[q * 4 + 3][km] = v.w;
        }
        __syncthreads();
#pragma unroll 8
        for (int kk = 0; kk < KC; kk++) {
            float a0 = As[ty * 4 + 0][kk];
            float a1 = As[ty * 4 + 1][kk];
            float a2 = As[ty * 4 + 2][kk];
            float a3 = As[ty * 4 + 3][kk];
            float b[11];
#pragma unroll
            for (int j = 0; j < 11; j++) b[j] = Bs[kk][tx * 11 + j];
#pragma unroll
            for (int j = 0; j < 11; j++) {
                acc[0][j] += a0 * b[j];
                acc[1][j] += a1 * b[j];
                acc[2][j] += a2 * b[j];
                acc[3][j] += a3 * b[j];
            }
        }
        __syncthreads();
    }
#pragma unroll
    for (int r = 0; r < 4; r++) {
        int row = row0 + ty * 4 + r;
        float rn = g_rnorm[row];
#pragma unroll
        for (int j = 0; j < 11; j++) {
            int col = tx * 11 + j;
            if (col < KM) out[(size_t)row * KM + col] = fabsf(acc[r][j] * rn);
        }
    }
}

__global__ void k_outcls(const float* __restrict__ out) {
    int idx = blockIdx.x * blockDim.x + threadIdx.x;
    if (idx >= NPTS * KPT) return;
    int n = idx / KPT, k = idx % KPT;
    const float* p = out + (size_t)n * KM + k * MPROTO;
    float m = p[0];
#pragma unroll
    for (int j = 1; j < MPROTO; j++) m = fmaxf(m, p[j]);
    g_outcls[idx] = m;
}

// per point: pred/conf_eff, kpt_class output, member count, E = exp(sim/eps),
// first sinkhorn column sum (r = 1).
__global__ void k_point(const float* __restrict__ logits, const int* __restrict__ gt,
                        const float* __restrict__ conf, float* __restrict__ d_out) {
    __shared__ float scs[KM];
    for (int i = threadIdx.x; i < KM; i += blockDim.x) scs[i] = 0.f;
    __syncthreads();
    int n = blockIdx.x * blockDim.x + threadIdx.x;    // exact grid
    float best = -1e30f; int pred = 0;
    float* kout = d_out + (size_t)NPTS * KM + NPTS + (size_t)n * KPT;
#pragma unroll
    for (int k = 0; k < KPT; k++) {
        float v = g_outcls[n * KPT + k];
        if (v > best) { best = v; pred = k; }
        kout[k] = fminf(fmaxf(v, 1e-4f), 1.0f - 1e-4f);
    }
    int g = gt[n];
    float ce = (g == pred) ? conf[n] : 0.0f;
    g_confeff[n] = ce;
    atomicAdd(&g_B[g], 1);
    const float* l = logits + (size_t)n * KM + g * MPROTO;
#pragma unroll
    for (int m = 0; m < MPROTO; m++) {
        float e = expf(l[m] / 0.05f);
        g_E[n * MPROTO + m] = e;
        atomicAdd(&scs[g * MPROTO + m], e);
    }
    __syncthreads();
    for (int i = threadIdx.x; i < KM; i += blockDim.x)
        atomicAdd(&g_cs[0][i], scs[i]);
}

__global__ void k_cupdate(int it) {
    int i = threadIdx.x;
    if (i < KM) g_c[it][i] = 1.0f / (10.0f * g_cs[it][i]);
}

// one sinkhorn iteration: row rescale r = 1/(B * sum_m c*E), then next colsum.
__global__ void k_iter(const int* __restrict__ gt, int cin, int cout) {
    __shared__ float sc[KM];
    __shared__ float scs[KM];
    for (int i = threadIdx.x; i < KM; i += blockDim.x) { sc[i] = g_c[cin][i]; scs[i] = 0.f; }
    __syncthreads();
    int n = blockIdx.x * blockDim.x + threadIdx.x;
    int g = gt[n];
    float E[MPROTO], s = 0.f;
#pragma unroll
    for (int m = 0; m < MPROTO; m++) { E[m] = g_E[n * MPROTO + m]; s += sc[g * MPROTO + m] * E[m]; }
    float r = 1.0f / ((float)g_B[g] * s);
#pragma unroll
    for (int m = 0; m < MPROTO; m++) atomicAdd(&scs[g * MPROTO + m], r * E[m]);
    __syncthreads();
    for (int i = threadIdx.x; i < KM; i += blockDim.x) atomicAdd(&g_cs[cout][i], scs[i]);
}

// final L = c3*E / sum(c3*E); idx=argmax L (proto_target); m* = argmax(L+gumbel).
__global__ void k_assign(const int* __restrict__ gt, float* __restrict__ d_out, GKeys keys) {
    __shared__ float sc[KM];
    for (int i = threadIdx.x; i < KM; i += blockDim.x) sc[i] = g_c[2][i];
    __syncthreads();
    int n = blockIdx.x * blockDim.x + threadIdx.x;
    int g = gt[n];
    float v[MPROTO], sv = 0.f, bestv = -1.f;
    int idx = 0;
#pragma unroll
    for (int m = 0; m < MPROTO; m++) {
        float val = sc[g * MPROTO + m] * g_E[n * MPROTO + m];
        v[m] = val; sv += val;
        if (val > bestv) { bestv = val; idx = m; }
    }
    d_out[(size_t)NPTS * KM + n] = (float)(idx + MPROTO * g);

    unsigned int ka = keys.a[g], kb = keys.b[g];
    float bestq = -1e30f; int mb = 0;
#pragma unroll
    for (int m = 0; m < MPROTO; m++) {
        float L = v[m] / sv;
        float q = L + gumbel_val(ka, kb, (unsigned int)(n * MPROTO + m));
        if (q > bestq) { bestq = q; mb = m; }
    }
    float ce = g_confeff[n];
    if (ce > 0.f) {
        atomicAdd(&g_nn[g * MPROTO + mb], ce);
        g_sel[n] = g * MPROTO + mb;
    } else {
        g_sel[n] = -1;
    }
}

// f[k,m,:] += conf_eff^2 * fhat[n,:] for assigned active points (~N/17 active).
__global__ void k_faccum(const float* __restrict__ feats) {
    int warp = (blockIdx.x * blockDim.x + threadIdx.x) >> 5;
    int lane = threadIdx.x & 31;
    if (warp >= NPTS) return;
    int sel = g_sel[warp];
    if (sel < 0) return;
    float ce = g_confeff[warp];
    float w = ce * ce * g_rnorm[warp];
    const float4* f = (const float4*)(feats + (size_t)warp * DIM);
    float* dst = g_fbuf + (size_t)sel * DIM;
#pragma unroll
    for (int i = 0; i < 6; i++) {
        float4 v = f[lane + i * 32];
        int o = (lane + i * 32) * 4;
        atomicAdd(dst + o + 0, w * v.x);
        atomicAdd(dst + o + 1, w * v.y);
        atomicAdd(dst + o + 2, w * v.z);
        atomicAdd(dst + o + 3, w * v.w);
    }
}

// new_protos = l2n(where(has & valid, 0.999*phat + 0.001*l2n(f), phat))
__global__ void k_newprotos(float* __restrict__ d_out) {
    int i = blockIdx.x;                  // 0..169
    int k = i / MPROTO;
    float nnv = g_nn[i];
    float hs = 0.f;
#pragma unroll
    for (int m = 0; m < MPROTO; m++) hs += g_nn[k * MPROTO + m];
    bool cond = (nnv != 0.f) && (hs > 0.f);

    float s = 0.f;
    for (int d = threadIdx.x; d < DIM; d += blockDim.x) { float v = g_fbuf[i * DIM + d]; s += v * v; }
    s = blockReduceSum(s);
    float fs = 1.0f / fmaxf(sqrtf(s), 1e-12f);

    float s2 = 0.f;
    for (int d = threadIdx.x; d < DIM; d += blockDim.x) {
        float p = g_phat[i * DIM + d];
        float b = cond ? 0.999f * p + 0.001f * (g_fbuf[i * DIM + d] * fs) : p;
        s2 += b * b;
    }
    s2 = blockReduceSum(s2);
    float bs = 1.0f / fmaxf(sqrtf(s2), 1e-12f);

    float* o = d_out + (size_t)NPTS * (KM + 1 + KPT) + (size_t)i * DIM;
    for (int d = threadIdx.x; d < DIM; d += blockDim.x) {
        float p = g_phat[i * DIM + d];
        float b = cond ? 0.999f * p + 0.001f * (g_fbuf[i * DIM + d] * fs) : p;
        o[d] = b * bs;
    }
}

// ---------------- launch -----------------------------------------------------
extern "C" void kernel_launch(void* const* d_in, const int* in_sizes, int n_in,
                              void* d_out, int out_size) {
    const float* feats  = (const float*)d_in[0];
    const int*   gt     = (const int*)d_in[1];
    const float* conf   = (const float*)d_in[2];
    const float* protos = (const float*)d_in[3];
    float* out = (float*)d_out;

    // JAX key(42) -> split(17), partitionable/foldlike: keys[k] = threefry((0,42),(0,k))
    GKeys keys;
    for (int k = 0; k < KPT; k++)
        threefry2x32(0u, 42u, 0u, (unsigned int)k, &keys.a[k], &keys.b[k]);

    k_zero<<<(KM * DIM + 255) / 256, 256>>>();
    k_protonorm<<<KM, 256>>>(protos);
    k_featnorm<<<NPTS / 8, 256>>>(feats);
    k_gemm<<<NPTS / TR, 256>>>(feats, out);
    k_outcls<<<(NPTS * KPT + 255) / 256, 256>>>(out);
    k_point<<<NPTS / 256, 256>>>(out, gt, conf, out);
    k_cupdate<<<1, 256>>>(0);
    k_iter<<<NPTS / 256, 256>>>(gt, 0, 1);
    k_cupdate<<<1, 256>>>(1);
    k_iter<<<NPTS / 256, 256>>>(gt, 1, 2);
    k_cupdate<<<1, 256>>>(2);
    k_assign<<<NPTS / 256, 256>>>(gt, out, keys);
    k_faccum<<<NPTS / 8, 256>>>(feats);
    k_newprotos<<<KM, 256>>>(out);
}

// round 14
// speedup vs baseline: 1.1064x; 1.1064x over previous
#include <cuda_runtime.h>
#include <cstdint>
#include <math.h>

#define NPTS   131072
#define DIM    768
#define KPT    17
#define MPROTO 10
#define KM     170      // KPT*MPROTO
#define KMP    192      // padded columns for GEMM tiling (16 threads * 12 cols)

// ---------------- scratch (__device__ globals; no allocation allowed) --------
__device__ float g_phat[KMP * DIM];     // normalized prototypes, padded rows zero
__device__ float g_rnorm[NPTS];         // 1/max(||feats_n||,1e-12)
__device__ float g_outcls[NPTS * KPT];  // max over m of |sim|
__device__ float g_confeff[NPTS];
__device__ float g_E[NPTS * MPROTO];    // exp(|sim[n, gt_n, m]| / eps)
__device__ float g_cs[3][KM];           // column sums per sinkhorn iter
__device__ float g_c[3][KM];            // column scales per sinkhorn iter
__device__ int   g_B[KPT];              // member counts
__device__ float g_nn[KM];              // n[k,m] counts (sum of conf_eff)
__device__ float g_fbuf[KM * DIM];      // f accumulator
__device__ int   g_sel[NPTS];           // assigned (k*10+m) or -1

struct GKeys { unsigned int a[KPT]; unsigned int b[KPT]; };

// ---------------- threefry2x32 (JAX-compatible, 20 rounds) -------------------
__host__ __device__ inline void threefry2x32(unsigned int k0, unsigned int k1,
                                             unsigned int x0, unsigned int x1,
                                             unsigned int* o0, unsigned int* o1) {
    unsigned int ks[3];
    ks[0] = k0; ks[1] = k1; ks[2] = k0 ^ k1 ^ 0x1BD11BDAu;
    x0 += ks[0]; x1 += ks[1];
    const unsigned int rotA[4] = {13u, 15u, 26u, 6u};
    const unsigned int rotB[4] = {17u, 29u, 16u, 24u};
#pragma unroll
    for (int i = 0; i < 5; i++) {
#pragma unroll
        for (int j = 0; j < 4; j++) {
            unsigned int r = (i & 1) ? rotB[j] : rotA[j];
            x0 += x1;
            x1 = (x1 << r) | (x1 >> (32u - r));
            x1 ^= x0;
        }
        x0 += ks[(i + 1) % 3];
        x1 += ks[(i + 2) % 3] + (unsigned int)(i + 1);
    }
    *o0 = x0; *o1 = x1;
}

__device__ __forceinline__ float gumbel_val(unsigned int ka, unsigned int kb,
                                            unsigned int idx) {
    unsigned int y0, y1;
    threefry2x32(ka, kb, 0u, idx, &y0, &y1);
    unsigned int bits = y0 ^ y1;
    float u = __uint_as_float((bits >> 9) | 0x3F800000u) - 1.0f;
    const float tiny = 1.17549435e-38f;
    u = fmaxf(u + tiny, tiny);
    return -logf(-logf(u));
}

// ---------------- f32x2 packed helpers ---------------------------------------
__device__ __forceinline__ unsigned long long packf2(float x, float y) {
    unsigned long long r;
    asm("mov.b64 %0, {%1, %2};" : "=l"(r) : "f"(x), "f"(y));
    return r;
}
__device__ __forceinline__ void unpackf2(unsigned long long v, float* x, float* y) {
    asm("mov.b64 {%0, %1}, %2;" : "=f"(*x), "=f"(*y) : "l"(v));
}
__device__ __forceinline__ void ffma2(unsigned long long& acc,
                                      unsigned long long a, unsigned long long b) {
    asm("fma.rn.f32x2 %0, %1, %2, %0;" : "+l"(acc) : "l"(a), "l"(b));
}

// ---------------- block reduction --------------------------------------------
__device__ __forceinline__ float blockReduceSum(float v) {
    __shared__ float sh[33];
    __syncthreads();
    int lane = threadIdx.x & 31, w = threadIdx.x >> 5;
#pragma unroll
    for (int o = 16; o; o >>= 1) v += __shfl_xor_sync(0xffffffffu, v, o);
    if (lane == 0) sh[w] = v;
    __syncthreads();
    int nw = (blockDim.x + 31) >> 5;
    v = (threadIdx.x < nw) ? sh[threadIdx.x] : 0.f;
    if (w == 0) {
#pragma unroll
        for (int o = 16; o; o >>= 1) v += __shfl_xor_sync(0xffffffffu, v, o);
        if (lane == 0) sh[32] = v;
    }
    __syncthreads();
    return sh[32];
}

// ---------------- kernels ----------------------------------------------------
__global__ void k_zero() {
    int i = blockIdx.x * blockDim.x + threadIdx.x;   // 130560 threads
    if (i < KM * DIM) g_fbuf[i] = 0.f;
    if (i < KM) { g_nn[i] = 0.f; g_cs[0][i] = 0.f; g_cs[1][i] = 0.f; g_cs[2][i] = 0.f; }
    if (i < KPT) g_B[i] = 0;
    if (i < (KMP - KM) * DIM) g_phat[KM * DIM + i] = 0.f;   // zero GEMM pad rows
}

__global__ void k_protonorm(const float* __restrict__ protos) {
    int r = blockIdx.x;                 // 0..169
    const float* p = protos + r * DIM;
    float s = 0.f;
    for (int i = threadIdx.x; i < DIM; i += blockDim.x) { float v = p[i]; s += v * v; }
    s = blockReduceSum(s);
    float sc = 1.0f / fmaxf(sqrtf(s), 1e-12f);
    for (int i = threadIdx.x; i < DIM; i += blockDim.x) g_phat[r * DIM + i] = p[i] * sc;
}

__global__ void k_featnorm(const float* __restrict__ feats) {
    int warp = (blockIdx.x * blockDim.x + threadIdx.x) >> 5;
    int lane = threadIdx.x & 31;
    if (warp >= NPTS) return;
    const float4* f = (const float4*)(feats + (size_t)warp * DIM);
    float s = 0.f;
#pragma unroll
    for (int i = 0; i < 6; i++) {
        float4 v = f[lane + i * 32];
        s += v.x * v.x + v.y * v.y + v.z * v.z + v.w * v.w;
    }
#pragma unroll
    for (int o = 16; o; o >>= 1) s += __shfl_xor_sync(0xffffffffu, s, o);
    if (lane == 0) g_rnorm[warp] = 1.0f / fmaxf(sqrtf(s), 1e-12f);
}

// C[N,170] = |(feats . phat^T) * rnorm| using packed FFMA2 (fma.rn.f32x2).
// 8 rows x 12 cols per thread; 256 threads -> 128-row x 192-col block tile.
#define TRN 128
#define KC 32
#define CPT 12
#define BS_STRIDE 196
#define AS_STRIDE 36
__global__ __launch_bounds__(256, 1) void k_gemm(const float* __restrict__ feats,
                                                 float* __restrict__ out) {
    __shared__ float As[TRN][AS_STRIDE];      // row-major tile of feats
    __shared__ float Bs[KC][BS_STRIDE];       // transposed phat tile: [k][col]
    int tx = threadIdx.x & 15;                // column group (12 cols each)
    int ty = threadIdx.x >> 4;                // row group (8 rows each)
    int row0 = blockIdx.x * TRN;
    int t = threadIdx.x;

    unsigned long long acc[8][6];
#pragma unroll
    for (int r = 0; r < 8; r++)
#pragma unroll
        for (int j = 0; j < 6; j++) acc[r][j] = 0ULL;

    for (int k0 = 0; k0 < DIM; k0 += KC) {
        // fill As: 128 rows x 8 float4 = 1024 vec loads, 4 per thread
#pragma unroll
        for (int it = 0; it < 4; it++) {
            int id = t + it * 256;
            int r = id >> 3;
            int q = id & 7;
            float4 v = *(const float4*)(feats + (size_t)(row0 + r) * DIM + k0 + q * 4);
            *(float4*)&As[r][q * 4] = v;
        }
        // fill Bs transposed: 192 cols x 8 float4 = 1536, 6 per thread
#pragma unroll
        for (int it = 0; it < 6; it++) {
            int id = t + it * 256;
            int km = id >> 3;
            int q = id & 7;
            float4 v = *(const float4*)(g_phat + km * DIM + k0 + q * 4);
            Bs[q * 4 + 0][km] = v.x; Bs[q * 4 + 1][km] = v.y;
            Bs[q * 4 + 2][km] = v.z; Bs[q * 4 + 3][km] = v.w;
        }
        __syncthreads();
#pragma unroll 8
        for (int kk = 0; kk < KC; kk++) {
            unsigned long long bP[6];
#pragma unroll
            for (int i = 0; i < 3; i++) {
                float4 v = *(const float4*)&Bs[kk][tx * CPT + i * 4];
                bP[2 * i + 0] = packf2(v.x, v.y);
                bP[2 * i + 1] = packf2(v.z, v.w);
            }
#pragma unroll
            for (int r = 0; r < 8; r++) {
                float a = As[ty * 8 + r][kk];
                unsigned long long aP = packf2(a, a);
#pragma unroll
                for (int j = 0; j < 6; j++) ffma2(acc[r][j], aP, bP[j]);
            }
        }
        __syncthreads();
    }
#pragma unroll
    for (int r = 0; r < 8; r++) {
        int row = row0 + ty * 8 + r;
        float rn = g_rnorm[row];
        float* orow = out + (size_t)row * KM;
#pragma unroll
        for (int j = 0; j < 6; j++) {
            float x, y;
            unpackf2(acc[r][j], &x, &y);
            int col = tx * CPT + 2 * j;
            if (col < KM)     orow[col]     = fabsf(x * rn);
            if (col + 1 < KM) orow[col + 1] = fabsf(y * rn);
        }
    }
}

__global__ void k_outcls(const float* __restrict__ out) {
    int idx = blockIdx.x * blockDim.x + threadIdx.x;
    if (idx >= NPTS * KPT) return;
    int n = idx / KPT, k = idx % KPT;
    const float* p = out + (size_t)n * KM + k * MPROTO;
    float m = p[0];
#pragma unroll
    for (int j = 1; j < MPROTO; j++) m = fmaxf(m, p[j]);
    g_outcls[idx] = m;
}

// per point: pred/conf_eff, kpt_class output, member count, E = exp(sim/eps),
// first sinkhorn column sum (r = 1).
__global__ void k_point(const float* __restrict__ logits, const int* __restrict__ gt,
                        const float* __restrict__ conf, float* __restrict__ d_out) {
    __shared__ float scs[KM];
    for (int i = threadIdx.x; i < KM; i += blockDim.x) scs[i] = 0.f;
    __syncthreads();
    int n = blockIdx.x * blockDim.x + threadIdx.x;    // exact grid
    float best = -1e30f; int pred = 0;
    float* kout = d_out + (size_t)NPTS * KM + NPTS + (size_t)n * KPT;
#pragma unroll
    for (int k = 0; k < KPT; k++) {
        float v = g_outcls[n * KPT + k];
        if (v > best) { best = v; pred = k; }
        kout[k] = fminf(fmaxf(v, 1e-4f), 1.0f - 1e-4f);
    }
    int g = gt[n];
    float ce = (g == pred) ? conf[n] : 0.0f;
    g_confeff[n] = ce;
    atomicAdd(&g_B[g], 1);
    const float* l = logits + (size_t)n * KM + g * MPROTO;
#pragma unroll
    for (int m = 0; m < MPROTO; m++) {
        float e = expf(l[m] / 0.05f);
        g_E[n * MPROTO + m] = e;
        atomicAdd(&scs[g * MPROTO + m], e);
    }
    __syncthreads();
    for (int i = threadIdx.x; i < KM; i += blockDim.x)
        atomicAdd(&g_cs[0][i], scs[i]);
}

__global__ void k_cupdate(int it) {
    int i = threadIdx.x;
    if (i < KM) g_c[it][i] = 1.0f / (10.0f * g_cs[it][i]);
}

// one sinkhorn iteration: row rescale r = 1/(B * sum_m c*E), then next colsum.
__global__ void k_iter(const int* __restrict__ gt, int cin, int cout) {
    __shared__ float sc[KM];
    __shared__ float scs[KM];
    for (int i = threadIdx.x; i < KM; i += blockDim.x) { sc[i] = g_c[cin][i]; scs[i] = 0.f; }
    __syncthreads();
    int n = blockIdx.x * blockDim.x + threadIdx.x;
    int g = gt[n];
    float E[MPROTO], s = 0.f;
#pragma unroll
    for (int m = 0; m < MPROTO; m++) { E[m] = g_E[n * MPROTO + m]; s += sc[g * MPROTO + m] * E[m]; }
    float r = 1.0f / ((float)g_B[g] * s);
#pragma unroll
    for (int m = 0; m < MPROTO; m++) atomicAdd(&scs[g * MPROTO + m], r * E[m]);
    __syncthreads();
    for (int i = threadIdx.x; i < KM; i += blockDim.x) atomicAdd(&g_cs[cout][i], scs[i]);
}

// final L = c3*E / sum(c3*E); idx=argmax L (proto_target); m* = argmax(L+gumbel).
__global__ void k_assign(const int* __restrict__ gt, float* __restrict__ d_out, GKeys keys) {
    __shared__ float sc[KM];
    for (int i = threadIdx.x; i < KM; i += blockDim.x) sc[i] = g_c[2][i];
    __syncthreads();
    int n = blockIdx.x * blockDim.x + threadIdx.x;
    int g = gt[n];
    float v[MPROTO], sv = 0.f, bestv = -1.f;
    int idx = 0;
#pragma unroll
    for (int m = 0; m < MPROTO; m++) {
        float val = sc[g * MPROTO + m] * g_E[n * MPROTO + m];
        v[m] = val; sv += val;
        if (val > bestv) { bestv = val; idx = m; }
    }
    d_out[(size_t)NPTS * KM + n] = (float)(idx + MPROTO * g);

    unsigned int ka = keys.a[g], kb = keys.b[g];
    float bestq = -1e30f; int mb = 0;
#pragma unroll
    for (int m = 0; m < MPROTO; m++) {
        float L = v[m] / sv;
        float q = L + gumbel_val(ka, kb, (unsigned int)(n * MPROTO + m));
        if (q > bestq) { bestq = q; mb = m; }
    }
    float ce = g_confeff[n];
    if (ce > 0.f) {
        atomicAdd(&g_nn[g * MPROTO + mb], ce);
        g_sel[n] = g * MPROTO + mb;
    } else {
        g_sel[n] = -1;
    }
}

// f[k,m,:] += conf_eff^2 * fhat[n,:] for assigned active points (~N/17 active).
__global__ void k_faccum(const float* __restrict__ feats) {
    int warp = (blockIdx.x * blockDim.x + threadIdx.x) >> 5;
    int lane = threadIdx.x & 31;
    if (warp >= NPTS) return;
    int sel = g_sel[warp];
    if (sel < 0) return;
    float ce = g_confeff[warp];
    float w = ce * ce * g_rnorm[warp];
    const float4* f = (const float4*)(feats + (size_t)warp * DIM);
    float* dst = g_fbuf + (size_t)sel * DIM;
#pragma unroll
    for (int i = 0; i < 6; i++) {
        float4 v = f[lane + i * 32];
        int o = (lane + i * 32) * 4;
        atomicAdd(dst + o + 0, w * v.x);
        atomicAdd(dst + o + 1, w * v.y);
        atomicAdd(dst + o + 2, w * v.z);
        atomicAdd(dst + o + 3, w * v.w);
    }
}

// new_protos = l2n(where(has & valid, 0.999*phat + 0.001*l2n(f), phat))
__global__ void k_newprotos(float* __restrict__ d_out) {
    int i = blockIdx.x;                  // 0..169
    int k = i / MPROTO;
    float nnv = g_nn[i];
    float hs = 0.f;
#pragma unroll
    for (int m = 0; m < MPROTO; m++) hs += g_nn[k * MPROTO + m];
    bool cond = (nnv != 0.f) && (hs > 0.f);

    float s = 0.f;
    for (int d = threadIdx.x; d < DIM; d += blockDim.x) { float v = g_fbuf[i * DIM + d]; s += v * v; }
    s = blockReduceSum(s);
    float fs = 1.0f / fmaxf(sqrtf(s), 1e-12f);

    float s2 = 0.f;
    for (int d = threadIdx.x; d < DIM; d += blockDim.x) {
        float p = g_phat[i * DIM + d];
        float b = cond ? 0.999f * p + 0.001f * (g_fbuf[i * DIM + d] * fs) : p;
        s2 += b * b;
    }
    s2 = blockReduceSum(s2);
    float bs = 1.0f / fmaxf(sqrtf(s2), 1e-12f);

    float* o = d_out + (size_t)NPTS * (KM + 1 + KPT) + (size_t)i * DIM;
    for (int d = threadIdx.x; d < DIM; d += blockDim.x) {
        float p = g_phat[i * DIM + d];
        float b = cond ? 0.999f * p + 0.001f * (g_fbuf[i * DIM + d] * fs) : p;
        o[d] = b * bs;
    }
}

// ---------------- launch -----------------------------------------------------
extern "C" void kernel_launch(void* const* d_in, const int* in_sizes, int n_in,
                              void* d_out, int out_size) {
    const float* feats  = (const float*)d_in[0];
    const int*   gt     = (const int*)d_in[1];
    const float* conf   = (const float*)d_in[2];
    const float* protos = (const float*)d_in[3];
    float* out = (float*)d_out;

    GKeys keys;
    for (int k = 0; k < KPT; k++)
        threefry2x32(0u, 42u, 0u, (unsigned int)k, &keys.a[k], &keys.b[k]);

    k_zero<<<(KM * DIM + 255) / 256, 256>>>();
    k_protonorm<<<KM, 256>>>(protos);
    k_featnorm<<<NPTS / 8, 256>>>(feats);
    k_gemm<<<NPTS / TRN, 256>>>(feats, out);
    k_outcls<<<(NPTS * KPT + 255) / 256, 256>>>(out);
    k_point<<<NPTS / 256, 256>>>(out, gt, conf, out);
    k_cupdate<<<1, 256>>>(0);
    k_iter<<<NPTS / 256, 256>>>(gt, 0, 1);
    k_cupdate<<<1, 256>>>(1);
    k_iter<<<NPTS / 256, 256>>>(gt, 1, 2);
    k_cupdate<<<1, 256>>>(2);
    k_assign<<<NPTS / 256, 256>>>(gt, out, keys);
    k_faccum<<<NPTS / 8, 256>>>(feats);
    k_newprotos<<<KM, 256>>>(out);
}